// round 5
// baseline (speedup 1.0000x reference)
#include <cuda_runtime.h>

// Stochastic-LIF eval-mode scan.
// x: [B=32, T=128, N=8192] f32, o: same shape.
// Recurrence per (b, n): u = 0.5*u + x_t; o = (u > 1); u = o ? 0 : u.
// Each thread owns one float4 (4 adjacent n) across all 128 time steps.
// T processed in chunks of 12; the 12 independent LDG.128 are issued via
// asm volatile so ptxas cannot sink them (true MLP=12).
// 64-thread blocks -> 1024 blocks: ~7 waves over 148 SMs, <2% wave-
// quantization loss (vs ~15% at 256 blocks).

static constexpr int B = 32;
static constexpr int T = 128;
static constexpr int N = 8192;
static constexpr int NV = N / 4;          // float4 columns per (b, t) row: 2048
static constexpr int CHAINS = B * NV;     // 65536 threads
static constexpr int CH = 12;             // time-chunk (prefetch depth)
// T = 128 = 10*12 + 8: handle the remainder with one CH=8 chunk.

__device__ __forceinline__ void lif_chunk(
    const float4* __restrict__ xp, float4* __restrict__ op,
    int t0, int len_const,           // len_const is a compile-time constant
    float& ux, float& uy, float& uz, float& uw)
{
    float xr[CH][4];
    #pragma unroll
    for (int i = 0; i < CH; ++i) {
        if (i < len_const) {
            const float4* p = xp + (size_t)(t0 + i) * NV;
            asm volatile("ld.global.cs.v4.f32 {%0,%1,%2,%3}, [%4];"
                         : "=f"(xr[i][0]), "=f"(xr[i][1]),
                           "=f"(xr[i][2]), "=f"(xr[i][3])
                         : "l"(p));
        }
    }
    #pragma unroll
    for (int i = 0; i < CH; ++i) {
        if (i < len_const) {
            ux = fmaf(0.5f, ux, xr[i][0]);
            uy = fmaf(0.5f, uy, xr[i][1]);
            uz = fmaf(0.5f, uz, xr[i][2]);
            uw = fmaf(0.5f, uw, xr[i][3]);

            float ox = (ux > 1.0f) ? 1.0f : 0.0f;
            float oy = (uy > 1.0f) ? 1.0f : 0.0f;
            float oz = (uz > 1.0f) ? 1.0f : 0.0f;
            float ow = (uw > 1.0f) ? 1.0f : 0.0f;

            ux = (ux > 1.0f) ? 0.0f : ux;
            uy = (uy > 1.0f) ? 0.0f : uy;
            uz = (uz > 1.0f) ? 0.0f : uz;
            uw = (uw > 1.0f) ? 0.0f : uw;

            float4* q = op + (size_t)(t0 + i) * NV;
            asm volatile("st.global.cs.v4.f32 [%0], {%1,%2,%3,%4};"
                         :: "l"(q), "f"(ox), "f"(oy), "f"(oz), "f"(ow)
                         : "memory");
        }
    }
}

__global__ void __launch_bounds__(64)
lif_scan_kernel(const float4* __restrict__ x, float4* __restrict__ o) {
    const int idx = blockIdx.x * blockDim.x + threadIdx.x;   // 0 .. CHAINS-1
    const int b = idx >> 11;          // / NV
    const int n = idx & (NV - 1);     // % NV

    const float4* __restrict__ xp = x + (size_t)b * T * NV + n;
    float4* __restrict__ op       = o + (size_t)b * T * NV + n;

    float ux = 0.f, uy = 0.f, uz = 0.f, uw = 0.f;

    // 10 chunks of 12 + 1 chunk of 8 = 128 steps
    #pragma unroll 1
    for (int c = 0; c < 10; ++c) {
        lif_chunk(xp, op, c * CH, CH, ux, uy, uz, uw);
    }
    lif_chunk(xp, op, 120, 8, ux, uy, uz, uw);
}

extern "C" void kernel_launch(void* const* d_in, const int* in_sizes, int n_in,
                              void* d_out, int out_size) {
    const float4* x = (const float4*)d_in[0];
    float4* o = (float4*)d_out;
    (void)in_sizes; (void)n_in; (void)out_size;

    const int threads = 64;
    const int blocks = CHAINS / threads;   // 1024
    lif_scan_kernel<<<blocks, threads>>>(x, o);
}